// round 15
// baseline (speedup 1.0000x reference)
#include <cuda_runtime.h>
#include <cuda_fp16.h>
#include <math.h>
#include <cstdint>

#define N_TOKEN 256
#define CP 128
#define H 4
#define NN (N_TOKEN * N_TOKEN)

// Scratch (allocation-free: __device__ globals) — activations fp16
__device__ __half g_q [NN * CP];
__device__ __half g_k [NN * CP];
__device__ __half g_v [NN * CP];
__device__ __half g_g [NN * CP];
__device__ float  g_b [H * NN];    // [h][j*256+k]
__device__ __half g_o [NN * CP];
// weights packed in mma-fragment order: [mat][warp_n][ks][lane][8 u32]
__device__ uint32_t g_wf[5 * 4 * 8 * 256];

// --------------------------------------------------------------- helpers
__device__ __forceinline__ unsigned smaddr(const void* p) {
    unsigned a;
    asm("{ .reg .u64 t; cvta.to.shared.u64 t, %1; cvt.u32.u64 %0, t; }"
        : "=r"(a) : "l"(p));
    return a;
}
__device__ __forceinline__ void ldsm4(uint32_t r[4], uint32_t a) {
    asm volatile("ldmatrix.sync.aligned.m8n8.x4.shared.b16 {%0,%1,%2,%3}, [%4];"
        : "=r"(r[0]), "=r"(r[1]), "=r"(r[2]), "=r"(r[3]) : "r"(a));
}
__device__ __forceinline__ void ldsm4t(uint32_t r[4], uint32_t a) {
    asm volatile("ldmatrix.sync.aligned.m8n8.x4.trans.shared.b16 {%0,%1,%2,%3}, [%4];"
        : "=r"(r[0]), "=r"(r[1]), "=r"(r[2]), "=r"(r[3]) : "r"(a));
}
__device__ __forceinline__ void mma16816(float c[4], const uint32_t a[4],
                                         uint32_t b0, uint32_t b1) {
    asm volatile(
        "mma.sync.aligned.m16n8k16.row.col.f32.f16.f16.f32 "
        "{%0,%1,%2,%3}, {%4,%5,%6,%7}, {%8,%9}, {%0,%1,%2,%3};"
        : "+f"(c[0]), "+f"(c[1]), "+f"(c[2]), "+f"(c[3])
        : "r"(a[0]), "r"(a[1]), "r"(a[2]), "r"(a[3]), "r"(b0), "r"(b1));
}
__device__ __forceinline__ uint32_t packh2(float lo, float hi) {
    __half2 h = __floats2half2_rn(lo, hi);
    return *(uint32_t*)&h;
}

// -------------------- weight pre-conversion to fragment order (once, ~2us)
// Fragment layout for thread (gid,tig), n-col group warp_n, k-step ks:
//   b0 = {W[k0+2tig][n], W[k0+2tig+1][n]}, b1 = {W[k0+2tig+8][n], W[k0+2tig+9][n]}
//   ordered (p0t0 b0,b1), (p0t1 b0,b1), (p1t0 b0,b1), (p1t1 b0,b1)
__global__ void k_wcvt(const float* __restrict__ Wq, const float* __restrict__ Wk,
                       const float* __restrict__ Wv, const float* __restrict__ Wg,
                       const float* __restrict__ Wout)
{
    const float* src[5] = {Wq, Wk, Wv, Wg, Wout};
    int t = blockIdx.x * 256 + threadIdx.x;     // 0..5119
    int lane = t & 31;
    int ks   = (t >> 5) & 7;
    int wn   = (t >> 8) & 3;
    int m    = t >> 10;                          // 0..4
    int gid = lane >> 2, tig = lane & 3;
    const float* W = src[m];

    uint32_t o[8];
    #pragma unroll
    for (int p = 0; p < 2; ++p)
        #pragma unroll
        for (int tt = 0; tt < 2; ++tt) {
            int n  = wn * 32 + p * 16 + tt * 8 + gid;
            int k0 = ks * 16 + 2 * tig;
            o[(p * 2 + tt) * 2 + 0] = packh2(W[(size_t)k0 * CP + n],
                                             W[(size_t)(k0 + 1) * CP + n]);
            o[(p * 2 + tt) * 2 + 1] = packh2(W[(size_t)(k0 + 8) * CP + n],
                                             W[(size_t)(k0 + 9) * CP + n]);
        }
    uint32_t* dst = g_wf + (((size_t)(m * 4 + wn) * 8 + ks) * 256 + lane * 8);
    *(uint4*)dst       = make_uint4(o[0], o[1], o[2], o[3]);
    *(uint4*)(dst + 4) = make_uint4(o[4], o[5], o[6], o[7]);
}

// ------------------- q/k/v/g projection with FUSED LayerNorm + bias (fp16 mma)
// A-only smem (17.4 KB); B fragments loaded directly from L2 (g_wf).
#define AS_H 136
#define PJ_SMEM (64 * AS_H * 2)

__global__ void __launch_bounds__(256, 3) k_proj_mma(
    const float* __restrict__ pair, const float* __restrict__ gamma,
    const float* __restrict__ beta, const float* __restrict__ Wb)
{
    extern __shared__ __half hsm[];
    __half* As = hsm;                  // [64][136]
    const uint32_t as_b = smaddr(As);

    const int tid = threadIdx.x;
    const int wid = tid >> 5, lane = tid & 31;
    const int warp_m = wid & 1, warp_n = wid >> 1;
    const int gid = lane >> 2, tig = lane & 3;
    const int m0 = blockIdx.x * 64;

    // ---- fused LN + bias: warp wid handles rows wid*8..+7 ----
    {
        float4 ga = *(const float4*)&gamma[lane * 4];
        float4 be = *(const float4*)&beta[lane * 4];
        #pragma unroll
        for (int rr = 0; rr < 8; ++rr) {
            const int r = wid * 8 + rr;
            const int row = m0 + r;
            float4 x = *(const float4*)&pair[(size_t)row * CP + lane * 4];
            float s = x.x + x.y + x.z + x.w;
            #pragma unroll
            for (int off = 16; off; off >>= 1)
                s += __shfl_xor_sync(0xffffffffu, s, off);
            float mu = s * (1.0f / CP);
            float4 d = make_float4(x.x - mu, x.y - mu, x.z - mu, x.w - mu);
            float sq = d.x * d.x + d.y * d.y + d.z * d.z + d.w * d.w;
            #pragma unroll
            for (int off = 16; off; off >>= 1)
                sq += __shfl_xor_sync(0xffffffffu, sq, off);
            float rstd = rsqrtf(sq * (1.0f / CP) + 1e-5f);
            float pn0 = d.x * rstd * ga.x + be.x;
            float pn1 = d.y * rstd * ga.y + be.y;
            float pn2 = d.z * rstd * ga.z + be.z;
            float pn3 = d.w * rstd * ga.w + be.w;
            __half2 hh[2] = {__floats2half2_rn(pn0, pn1), __floats2half2_rn(pn2, pn3)};
            *(uint2*)&As[r * AS_H + lane * 4] = *(uint2*)hh;

            float pe[4] = {pn0, pn1, pn2, pn3};
            float pb[4] = {0.f, 0.f, 0.f, 0.f};
            #pragma unroll
            for (int e = 0; e < 4; ++e) {
                float4 wb = *(const float4*)&Wb[(lane * 4 + e) * 4];
                pb[0] += pe[e] * wb.x; pb[1] += pe[e] * wb.y;
                pb[2] += pe[e] * wb.z; pb[3] += pe[e] * wb.w;
            }
            #pragma unroll
            for (int h = 0; h < 4; ++h) {
                #pragma unroll
                for (int off = 16; off; off >>= 1)
                    pb[h] += __shfl_xor_sync(0xffffffffu, pb[h], off);
            }
            if (lane < 4) g_b[lane * NN + row] = pb[lane];
        }
    }
    __syncthreads();   // As visible to all warps

    __half* Os[4] = {g_q, g_k, g_v, g_g};

    #pragma unroll
    for (int mat = 0; mat < 4; ++mat) {
        const uint32_t* wf = g_wf +
            (((size_t)(mat * 4 + warp_n) * 8) * 256 + lane * 8);

        float c[2][4][4];
        #pragma unroll
        for (int mf = 0; mf < 2; ++mf)
            #pragma unroll
            for (int nt = 0; nt < 4; ++nt)
                #pragma unroll
                for (int q = 0; q < 4; ++q) c[mf][nt][q] = 0.f;

        #pragma unroll
        for (int ks = 0; ks < 8; ++ks) {
            const int k0 = ks * 16;
            uint32_t a[2][4];
            #pragma unroll
            for (int mf = 0; mf < 2; ++mf)
                ldsm4(a[mf], as_b +
                    ((warp_m * 32 + mf * 16 + (lane & 15)) * AS_H + k0 + (lane >> 4) * 8) * 2);
            uint4 lo = *(const uint4*)(wf + ks * 256);
            uint4 hi = *(const uint4*)(wf + ks * 256 + 4);
            #pragma unroll
            for (int mf = 0; mf < 2; ++mf) {
                mma16816(c[mf][0], a[mf], lo.x, lo.y);
                mma16816(c[mf][1], a[mf], lo.z, lo.w);
                mma16816(c[mf][2], a[mf], hi.x, hi.y);
                mma16816(c[mf][3], a[mf], hi.z, hi.w);
            }
        }

        __half* O = Os[mat];
        #pragma unroll
        for (int mf = 0; mf < 2; ++mf) {
            #pragma unroll
            for (int nt = 0; nt < 4; ++nt) {
                int r  = m0 + warp_m * 32 + mf * 16 + gid;
                int cb = warp_n * 32 + nt * 8 + tig * 2;
                float v0 = c[mf][nt][0], v1 = c[mf][nt][1];
                float v2 = c[mf][nt][2], v3 = c[mf][nt][3];
                if (mat == 3) {
                    v0 = 1.f / (1.f + __expf(-v0));
                    v1 = 1.f / (1.f + __expf(-v1));
                    v2 = 1.f / (1.f + __expf(-v2));
                    v3 = 1.f / (1.f + __expf(-v3));
                }
                *(__half2*)&O[(size_t)r * CP + cb]       = __floats2half2_rn(v0, v1);
                *(__half2*)&O[(size_t)(r + 8) * CP + cb] = __floats2half2_rn(v2, v3);
            }
        }
    }
}

// ----------------------------------------------- output projection (fp16 mma)
__global__ void __launch_bounds__(256, 3) k_out_mma(float* __restrict__ out)
{
    extern __shared__ __half hsm[];
    __half* As = hsm;
    const uint32_t as_b = smaddr(As);

    const int tid = threadIdx.x;
    const int wid = tid >> 5, lane = tid & 31;
    const int warp_m = wid & 1, warp_n = wid >> 1;
    const int gid = lane >> 2, tig = lane & 3;
    const int m0 = blockIdx.x * 64;

    {
        const __half* src = g_o + (size_t)m0 * CP;
        #pragma unroll
        for (int it = 0; it < 4; ++it) {
            int idx = tid + it * 256;
            int r = idx >> 4, u = idx & 15;
            *(uint4*)&As[r * AS_H + u * 8] = *(const uint4*)&src[(size_t)r * CP + u * 8];
        }
    }
    __syncthreads();

    const uint32_t* wf = g_wf +
        (((size_t)(4 * 4 + warp_n) * 8) * 256 + lane * 8);

    float c[2][4][4];
    #pragma unroll
    for (int mf = 0; mf < 2; ++mf)
        #pragma unroll
        for (int nt = 0; nt < 4; ++nt)
            #pragma unroll
            for (int q = 0; q < 4; ++q) c[mf][nt][q] = 0.f;

    #pragma unroll
    for (int ks = 0; ks < 8; ++ks) {
        const int k0 = ks * 16;
        uint32_t a[2][4];
        #pragma unroll
        for (int mf = 0; mf < 2; ++mf)
            ldsm4(a[mf], as_b +
                ((warp_m * 32 + mf * 16 + (lane & 15)) * AS_H + k0 + (lane >> 4) * 8) * 2);
        uint4 lo = *(const uint4*)(wf + ks * 256);
        uint4 hi = *(const uint4*)(wf + ks * 256 + 4);
        #pragma unroll
        for (int mf = 0; mf < 2; ++mf) {
            mma16816(c[mf][0], a[mf], lo.x, lo.y);
            mma16816(c[mf][1], a[mf], lo.z, lo.w);
            mma16816(c[mf][2], a[mf], hi.x, hi.y);
            mma16816(c[mf][3], a[mf], hi.z, hi.w);
        }
    }

    #pragma unroll
    for (int mf = 0; mf < 2; ++mf) {
        #pragma unroll
        for (int nt = 0; nt < 4; ++nt) {
            int r  = m0 + warp_m * 32 + mf * 16 + gid;
            int cb = warp_n * 32 + nt * 8 + tig * 2;
            *(float2*)&out[(size_t)r * CP + cb] =
                make_float2(c[mf][nt][0], c[mf][nt][1]);
            *(float2*)&out[(size_t)(r + 8) * CP + cb] =
                make_float2(c[mf][nt][2], c[mf][nt][3]);
        }
    }
}

// ------------------------------------------------ attention (fp16 mma)
// One CTA per (i,h), 8 warps, 8 j-tiles of 32, 3 CTAs/SM.
// No softmax reductions: denominator via parallel mma against ones-column.
#define KS_H 40          // half stride for K/V/Q rows
#define S_S  260         // f32 stride for S rows (520 halves aliased)
#define OFF_K 0
#define OFF_V 20480
#define OFF_Q 40960
#define OFF_S 43520
#define ATTN_SMEM (43520 + 32 * S_S * 4)

__global__ void __launch_bounds__(256, 3) k_attn_mma()
{
    extern __shared__ char csm[];
    __half* Ks = (__half*)(csm + OFF_K);   // [256][40]
    __half* Vs = (__half*)(csm + OFF_V);   // [256][40]
    __half* Qs = (__half*)(csm + OFF_Q);   // [32][40]  current j-tile
    float*  Sf = (float*)(csm + OFF_S);    // [32][260] f32 logits
    __half* Ph = (__half*)(csm + OFF_S);   // aliased exp tile, stride 520
    const uint32_t ks_b = smaddr(Ks), vs_b = smaddr(Vs);
    const uint32_t qs_b = smaddr(Qs), ph_b = smaddr(Ph);

    const int i = blockIdx.x, h = blockIdx.y;
    const int tid = threadIdx.x;
    const int wid = tid >> 5, lane = tid & 31;
    const int gid = lane >> 2, tig = lane & 3;
    const float scale = 0.17677669529663687f;  // 1/sqrt(32)

    const __half* gk = g_k + ((size_t)i * 256) * CP + h * 32;
    const __half* gv = g_v + ((size_t)i * 256) * CP + h * 32;
    const __half* gq = g_q + ((size_t)i * 256) * CP + h * 32;
    const __half* gg = g_g + ((size_t)i * 256) * CP + h * 32;
    __half*       go = g_o + ((size_t)i * 256) * CP + h * 32;
    const float* __restrict__ gb = g_b + (size_t)h * NN;

    // stage K, V (once) + Q tile 0
    #pragma unroll
    for (int it = 0; it < 4; ++it) {
        int idx = tid + it * 256;         // 0..1023
        int kk = idx >> 2, u = idx & 3;
        *(uint4*)&Ks[kk * KS_H + u * 8] = *(const uint4*)&gk[(size_t)kk * CP + u * 8];
        *(uint4*)&Vs[kk * KS_H + u * 8] = *(const uint4*)&gv[(size_t)kk * CP + u * 8];
    }
    if (tid < 128) {
        int r = tid >> 2, u = tid & 3;
        *(uint4*)&Qs[r * KS_H + u * 8] = *(const uint4*)&gq[(size_t)r * CP + u * 8];
    }
    __syncthreads();

    // constant B fragment: ones in local col 0 (denominator column)
    const uint32_t bONE = (gid == 0) ? 0x3C003C00u : 0u;

    for (int jt = 0; jt < 8; ++jt) {
        const int j0 = jt * 32;

        // ---- S = Q K^T : warp wid covers keys wid*32..+31, rows 0..31 ----
        {
            float c[2][4][4];
            #pragma unroll
            for (int mf = 0; mf < 2; ++mf)
                #pragma unroll
                for (int nt = 0; nt < 4; ++nt)
                    #pragma unroll
                    for (int q = 0; q < 4; ++q) c[mf][nt][q] = 0.f;

            #pragma unroll
            for (int ks = 0; ks < 2; ++ks) {
                const int k0 = ks * 16;
                uint32_t a[2][4], b[2][4];
                #pragma unroll
                for (int mf = 0; mf < 2; ++mf)
                    ldsm4(a[mf], qs_b +
                        ((mf * 16 + (lane & 15)) * KS_H + k0 + (lane >> 4) * 8) * 2);
                #pragma unroll
                for (int p = 0; p < 2; ++p)
                    ldsm4(b[p], ks_b +
                        ((wid * 32 + p * 16 + (lane & 7) + (lane >> 4) * 8) * KS_H
                         + k0 + ((lane >> 3) & 1) * 8) * 2);
                #pragma unroll
                for (int mf = 0; mf < 2; ++mf)
                    #pragma unroll
                    for (int p = 0; p < 2; ++p)
                        #pragma unroll
                        for (int t = 0; t < 2; ++t)
                            mma16816(c[mf][p * 2 + t], a[mf], b[p][t * 2], b[p][t * 2 + 1]);
            }
            #pragma unroll
            for (int mf = 0; mf < 2; ++mf)
                #pragma unroll
                for (int nt = 0; nt < 4; ++nt) {
                    int r = mf * 16 + gid;
                    int cb = wid * 32 + nt * 8 + tig * 2;
                    *(float2*)&Sf[r * S_S + cb] = make_float2(c[mf][nt][0], c[mf][nt][1]);
                    *(float2*)&Sf[(r + 8) * S_S + cb] = make_float2(c[mf][nt][2], c[mf][nt][3]);
                }
        }
        __syncthreads();

        // ---- softmax exp (streaming, no reductions): warp owns rows wid*4..+3 ----
        #pragma unroll
        for (int rr = 0; rr < 4; ++rr) {
            const int r = wid * 4 + rr;
            const int jg = j0 + r;
            float4 s0 = *(float4*)&Sf[r * S_S + lane * 8];
            float4 s1 = *(float4*)&Sf[r * S_S + lane * 8 + 4];
            float4 b0 = *(const float4*)&gb[(size_t)jg * 256 + lane * 8];
            float4 b1 = *(const float4*)&gb[(size_t)jg * 256 + lane * 8 + 4];
            float e0 = __expf(fmaf(s0.x, scale, b0.x));
            float e1 = __expf(fmaf(s0.y, scale, b0.y));
            float e2 = __expf(fmaf(s0.z, scale, b0.z));
            float e3 = __expf(fmaf(s0.w, scale, b0.w));
            float e4 = __expf(fmaf(s1.x, scale, b1.x));
            float e5 = __expf(fmaf(s1.y, scale, b1.y));
            float e6 = __expf(fmaf(s1.z, scale, b1.z));
            float e7 = __expf(fmaf(s1.w, scale, b1.w));
            __half2 hh[4] = {__floats2half2_rn(e0, e1), __floats2half2_rn(e2, e3),
                             __floats2half2_rn(e4, e5), __floats2half2_rn(e6, e7)};
            *(uint4*)&Ph[r * (S_S * 2) + lane * 8] = *(uint4*)hh;
        }
        __syncthreads();

        // ---- pipelined Q stage for next tile (threads 0-127) + PV ----
        if (jt < 7 && tid < 128) {
            int r = tid >> 2, u = tid & 3;
            *(uint4*)&Qs[r * KS_H + u * 8] =
                *(const uint4*)&gq[(size_t)(j0 + 32 + r) * CP + u * 8];
        }

        // ---- O = P V + denominator mma: warp (wm rows, wn cols), K=256 ----
        {
            const int wm = wid & 1, wn = wid >> 1;
            float o[4]  = {0.f, 0.f, 0.f, 0.f};
            float od[4] = {0.f, 0.f, 0.f, 0.f};
            #pragma unroll
            for (int kc = 0; kc < 8; ++kc) {
                const int k0 = kc * 32;
                uint32_t a0[4], a1[4], bv[4];
                ldsm4(a0, ph_b +
                    ((wm * 16 + (lane & 15)) * (S_S * 2) + k0 + (lane >> 4) * 8) * 2);
                ldsm4(a1, ph_b +
                    ((wm * 16 + (lane & 15)) * (S_S * 2) + k0 + 16 + (lane >> 4) * 8) * 2);
                ldsm4t(bv, vs_b + ((k0 + lane) * KS_H + wn * 8) * 2);
                mma16816(o, a0, bv[0], bv[1]);
                mma16816(o, a1, bv[2], bv[3]);
                mma16816(od, a0, bONE, bONE);
                mma16816(od, a1, bONE, bONE);
            }
            // denominator lives in tig==0 lanes (local col 0): broadcast
            float den0 = __shfl_sync(0xffffffffu, od[0], lane & ~3);
            float den1 = __shfl_sync(0xffffffffu, od[2], lane & ~3);
            const int r = wm * 16 + gid;
            const int cc = wn * 8 + tig * 2;
            float i0 = 1.f / den0, i1 = 1.f / den1;
            float2 gf0 = __half22float2(*(const __half2*)&gg[(size_t)(j0 + r) * CP + cc]);
            float2 gf1 = __half22float2(*(const __half2*)&gg[(size_t)(j0 + r + 8) * CP + cc]);
            *(__half2*)&go[(size_t)(j0 + r) * CP + cc] =
                __floats2half2_rn(o[0] * i0 * gf0.x, o[1] * i0 * gf0.y);
            *(__half2*)&go[(size_t)(j0 + r + 8) * CP + cc] =
                __floats2half2_rn(o[2] * i1 * gf1.x, o[3] * i1 * gf1.y);
        }
        __syncthreads();   // protect S/P (next QK writes) + Qs (next QK reads)
    }
}

// ----------------------------------------------------------------- launcher
extern "C" void kernel_launch(void* const* d_in, const int* in_sizes, int n_in,
                              void* d_out, int out_size)
{
    const float* pair  = (const float*)d_in[0];
    const float* gamma = (const float*)d_in[1];
    const float* beta  = (const float*)d_in[2];
    const float* Wq    = (const float*)d_in[3];
    const float* Wk    = (const float*)d_in[4];
    const float* Wv    = (const float*)d_in[5];
    const float* Wb    = (const float*)d_in[6];
    const float* Wg    = (const float*)d_in[7];
    const float* Wout  = (const float*)d_in[8];
    float* out = (float*)d_out;

    cudaFuncSetAttribute(k_proj_mma, cudaFuncAttributeMaxDynamicSharedMemorySize, PJ_SMEM);
    cudaFuncSetAttribute(k_out_mma,  cudaFuncAttributeMaxDynamicSharedMemorySize, PJ_SMEM);
    cudaFuncSetAttribute(k_attn_mma, cudaFuncAttributeMaxDynamicSharedMemorySize, ATTN_SMEM);

    k_wcvt    <<<20, 256>>>(Wq, Wk, Wv, Wg, Wout);
    k_proj_mma<<<NN / 64, 256, PJ_SMEM>>>(pair, gamma, beta, Wb);
    k_attn_mma<<<dim3(N_TOKEN, H), 256, ATTN_SMEM>>>();
    k_out_mma <<<NN / 64, 256, PJ_SMEM>>>(out);
}

// round 16
// speedup vs baseline: 1.2419x; 1.2419x over previous
#include <cuda_runtime.h>
#include <cuda_fp16.h>
#include <math.h>
#include <cstdint>

#define N_TOKEN 256
#define CP 128
#define H 4
#define NN (N_TOKEN * N_TOKEN)

// Scratch (allocation-free: __device__ globals) — activations fp16
__device__ __half g_q [NN * CP];
__device__ __half g_k [NN * CP];
__device__ __half g_v [NN * CP];
__device__ __half g_g [NN * CP];
__device__ __half g_b [H * NN];       // [h][j*256+k] pairwise bias (fp16)
__device__ __half g_o [NN * CP];
__device__ __half g_wh[5 * CP * CP];  // fp16 weights: Wq,Wk,Wv,Wg,Wout

// --------------------------------------------------------------- helpers
__device__ __forceinline__ unsigned smaddr(const void* p) {
    unsigned a;
    asm("{ .reg .u64 t; cvta.to.shared.u64 t, %1; cvt.u32.u64 %0, t; }"
        : "=r"(a) : "l"(p));
    return a;
}
__device__ __forceinline__ void ldsm4(uint32_t r[4], uint32_t a) {
    asm volatile("ldmatrix.sync.aligned.m8n8.x4.shared.b16 {%0,%1,%2,%3}, [%4];"
        : "=r"(r[0]), "=r"(r[1]), "=r"(r[2]), "=r"(r[3]) : "r"(a));
}
__device__ __forceinline__ void ldsm4t(uint32_t r[4], uint32_t a) {
    asm volatile("ldmatrix.sync.aligned.m8n8.x4.trans.shared.b16 {%0,%1,%2,%3}, [%4];"
        : "=r"(r[0]), "=r"(r[1]), "=r"(r[2]), "=r"(r[3]) : "r"(a));
}
__device__ __forceinline__ void mma16816(float c[4], const uint32_t a[4],
                                         uint32_t b0, uint32_t b1) {
    asm volatile(
        "mma.sync.aligned.m16n8k16.row.col.f32.f16.f16.f32 "
        "{%0,%1,%2,%3}, {%4,%5,%6,%7}, {%8,%9}, {%0,%1,%2,%3};"
        : "+f"(c[0]), "+f"(c[1]), "+f"(c[2]), "+f"(c[3])
        : "r"(a[0]), "r"(a[1]), "r"(a[2]), "r"(a[3]), "r"(b0), "r"(b1));
}

// ---------------------------------------------- weight pre-conversion (once)
__global__ void k_wcvt(const float* __restrict__ Wq, const float* __restrict__ Wk,
                       const float* __restrict__ Wv, const float* __restrict__ Wg,
                       const float* __restrict__ Wout)
{
    const float* src[5] = {Wq, Wk, Wv, Wg, Wout};
    int t = blockIdx.x * 256 + threadIdx.x;    // 0..20479
    int m = t >> 12;                           // matrix index
    int e = (t & 4095) * 4;                    // element base
    float4 v = *(const float4*)&src[m][e];
    __half2 hh[2] = {__floats2half2_rn(v.x, v.y), __floats2half2_rn(v.z, v.w)};
    *(uint2*)&g_wh[m * (CP * CP) + e] = *(uint2*)hh;
}

// ------------------- q/k/v/g projection with FUSED LayerNorm + bias (fp16 mma)
#define AS_H 136
#define BS_H 136
#define PJ_SMEM ((64 * AS_H + 128 * BS_H) * 2)

__global__ void __launch_bounds__(256, 3) k_proj_mma(
    const float* __restrict__ pair, const float* __restrict__ gamma,
    const float* __restrict__ beta, const float* __restrict__ Wb)
{
    extern __shared__ __half hsm[];
    __half* As = hsm;                  // [64][136]
    __half* Bs = hsm + 64 * AS_H;      // [128][136] k-major
    const uint32_t as_b = smaddr(As), bs_b = smaddr(Bs);

    const int tid = threadIdx.x;
    const int wid = tid >> 5, lane = tid & 31;
    const int warp_m = wid & 1, warp_n = wid >> 1;
    const int gid = lane >> 2, tig = lane & 3;
    const int m0 = blockIdx.x * 64;

    // ---- fused LN + bias: warp wid handles rows wid*8..+7 ----
    {
        float4 ga = *(const float4*)&gamma[lane * 4];
        float4 be = *(const float4*)&beta[lane * 4];
        #pragma unroll
        for (int rr = 0; rr < 8; ++rr) {
            const int r = wid * 8 + rr;
            const int row = m0 + r;
            float4 x = *(const float4*)&pair[(size_t)row * CP + lane * 4];
            float s = x.x + x.y + x.z + x.w;
            #pragma unroll
            for (int off = 16; off; off >>= 1)
                s += __shfl_xor_sync(0xffffffffu, s, off);
            float mu = s * (1.0f / CP);
            float4 d = make_float4(x.x - mu, x.y - mu, x.z - mu, x.w - mu);
            float sq = d.x * d.x + d.y * d.y + d.z * d.z + d.w * d.w;
            #pragma unroll
            for (int off = 16; off; off >>= 1)
                sq += __shfl_xor_sync(0xffffffffu, sq, off);
            float rstd = rsqrtf(sq * (1.0f / CP) + 1e-5f);
            float pn0 = d.x * rstd * ga.x + be.x;
            float pn1 = d.y * rstd * ga.y + be.y;
            float pn2 = d.z * rstd * ga.z + be.z;
            float pn3 = d.w * rstd * ga.w + be.w;
            __half2 hh[2] = {__floats2half2_rn(pn0, pn1), __floats2half2_rn(pn2, pn3)};
            *(uint2*)&As[r * AS_H + lane * 4] = *(uint2*)hh;

            float pe[4] = {pn0, pn1, pn2, pn3};
            float pb[4] = {0.f, 0.f, 0.f, 0.f};
            #pragma unroll
            for (int e = 0; e < 4; ++e) {
                float4 wb = *(const float4*)&Wb[(lane * 4 + e) * 4];
                pb[0] += pe[e] * wb.x; pb[1] += pe[e] * wb.y;
                pb[2] += pe[e] * wb.z; pb[3] += pe[e] * wb.w;
            }
            #pragma unroll
            for (int h = 0; h < 4; ++h) {
                #pragma unroll
                for (int off = 16; off; off >>= 1)
                    pb[h] += __shfl_xor_sync(0xffffffffu, pb[h], off);
            }
            if (lane < 4) g_b[lane * NN + row] = __float2half_rn(pb[lane]);
        }
    }

    __half* Os[4] = {g_q, g_k, g_v, g_g};

    #pragma unroll
    for (int mat = 0; mat < 4; ++mat) {
        if (mat > 0) __syncthreads();   // Bs reads from previous mat done
        // stage B: pure fp16 copy (pre-converted weights)
        {
            const __half* Wsrc = g_wh + mat * (CP * CP);
            #pragma unroll
            for (int it = 0; it < 8; ++it) {
                int idx = tid + it * 256;        // 0..2047 uint4
                int k = idx >> 4, u = idx & 15;
                *(uint4*)&Bs[k * BS_H + u * 8] = *(const uint4*)&Wsrc[k * CP + u * 8];
            }
        }
        __syncthreads();

        float c[2][4][4];
        #pragma unroll
        for (int mf = 0; mf < 2; ++mf)
            #pragma unroll
            for (int nt = 0; nt < 4; ++nt)
                #pragma unroll
                for (int q = 0; q < 4; ++q) c[mf][nt][q] = 0.f;

        #pragma unroll
        for (int ks = 0; ks < 8; ++ks) {
            const int k0 = ks * 16;
            uint32_t a[2][4], b[2][4];
            #pragma unroll
            for (int mf = 0; mf < 2; ++mf)
                ldsm4(a[mf], as_b +
                    ((warp_m * 32 + mf * 16 + (lane & 15)) * AS_H + k0 + (lane >> 4) * 8) * 2);
            #pragma unroll
            for (int p = 0; p < 2; ++p)
                ldsm4t(b[p], bs_b +
                    ((k0 + (lane & 15)) * BS_H + warp_n * 32 + p * 16 + (lane >> 4) * 8) * 2);
            #pragma unroll
            for (int mf = 0; mf < 2; ++mf)
                #pragma unroll
                for (int p = 0; p < 2; ++p)
                    #pragma unroll
                    for (int t = 0; t < 2; ++t)
                        mma16816(c[mf][p * 2 + t], a[mf], b[p][t * 2], b[p][t * 2 + 1]);
        }

        __half* O = Os[mat];
        #pragma unroll
        for (int mf = 0; mf < 2; ++mf) {
            #pragma unroll
            for (int nt = 0; nt < 4; ++nt) {
                int r  = m0 + warp_m * 32 + mf * 16 + gid;
                int cb = warp_n * 32 + nt * 8 + tig * 2;
                float v0 = c[mf][nt][0], v1 = c[mf][nt][1];
                float v2 = c[mf][nt][2], v3 = c[mf][nt][3];
                if (mat == 3) {
                    v0 = 1.f / (1.f + __expf(-v0));
                    v1 = 1.f / (1.f + __expf(-v1));
                    v2 = 1.f / (1.f + __expf(-v2));
                    v3 = 1.f / (1.f + __expf(-v3));
                }
                *(__half2*)&O[(size_t)r * CP + cb]       = __floats2half2_rn(v0, v1);
                *(__half2*)&O[(size_t)(r + 8) * CP + cb] = __floats2half2_rn(v2, v3);
            }
        }
    }
}

// ----------------------------------------------- output projection (fp16 mma)
__global__ void __launch_bounds__(256, 3) k_out_mma(float* __restrict__ out)
{
    extern __shared__ __half hsm[];
    __half* As = hsm;
    __half* Bs = hsm + 64 * AS_H;
    const uint32_t as_b = smaddr(As), bs_b = smaddr(Bs);

    const int tid = threadIdx.x;
    const int wid = tid >> 5, lane = tid & 31;
    const int warp_m = wid & 1, warp_n = wid >> 1;
    const int gid = lane >> 2, tig = lane & 3;
    const int m0 = blockIdx.x * 64;

    {
        const __half* src = g_o + (size_t)m0 * CP;
        #pragma unroll
        for (int it = 0; it < 4; ++it) {
            int idx = tid + it * 256;
            int r = idx >> 4, u = idx & 15;
            *(uint4*)&As[r * AS_H + u * 8] = *(const uint4*)&src[(size_t)r * CP + u * 8];
        }
    }
    {
        const __half* Wsrc = g_wh + 4 * (CP * CP);
        #pragma unroll
        for (int it = 0; it < 8; ++it) {
            int idx = tid + it * 256;
            int k = idx >> 4, u = idx & 15;
            *(uint4*)&Bs[k * BS_H + u * 8] = *(const uint4*)&Wsrc[k * CP + u * 8];
        }
    }
    __syncthreads();

    float c[2][4][4];
    #pragma unroll
    for (int mf = 0; mf < 2; ++mf)
        #pragma unroll
        for (int nt = 0; nt < 4; ++nt)
            #pragma unroll
            for (int q = 0; q < 4; ++q) c[mf][nt][q] = 0.f;

    #pragma unroll
    for (int ks = 0; ks < 8; ++ks) {
        const int k0 = ks * 16;
        uint32_t a[2][4], b[2][4];
        #pragma unroll
        for (int mf = 0; mf < 2; ++mf)
            ldsm4(a[mf], as_b +
                ((warp_m * 32 + mf * 16 + (lane & 15)) * AS_H + k0 + (lane >> 4) * 8) * 2);
        #pragma unroll
        for (int p = 0; p < 2; ++p)
            ldsm4t(b[p], bs_b +
                ((k0 + (lane & 15)) * BS_H + warp_n * 32 + p * 16 + (lane >> 4) * 8) * 2);
        #pragma unroll
        for (int mf = 0; mf < 2; ++mf)
            #pragma unroll
            for (int p = 0; p < 2; ++p)
                #pragma unroll
                for (int t = 0; t < 2; ++t)
                    mma16816(c[mf][p * 2 + t], a[mf], b[p][t * 2], b[p][t * 2 + 1]);
    }

    #pragma unroll
    for (int mf = 0; mf < 2; ++mf) {
        #pragma unroll
        for (int nt = 0; nt < 4; ++nt) {
            int r  = m0 + warp_m * 32 + mf * 16 + gid;
            int cb = warp_n * 32 + nt * 8 + tig * 2;
            *(float2*)&out[(size_t)r * CP + cb] =
                make_float2(c[mf][nt][0], c[mf][nt][1]);
            *(float2*)&out[(size_t)(r + 8) * CP + cb] =
                make_float2(c[mf][nt][2], c[mf][nt][3]);
        }
    }
}

// ------------------------------------------------ attention (fp16 mma)
// One CTA per (i,h), 8 warps, 8 j-tiles of 32, 3 CTAs/SM.
// No softmax reductions: denominator via parallel mma against ones-column.
#define KS_H 40          // half stride for K/V/Q rows
#define S_S  260         // f32 stride for S rows (520 halves aliased)
#define OFF_K 0
#define OFF_V 20480
#define OFF_Q 40960
#define OFF_S 43520
#define ATTN_SMEM (43520 + 32 * S_S * 4)

__global__ void __launch_bounds__(256, 3) k_attn_mma()
{
    extern __shared__ char csm[];
    __half* Ks = (__half*)(csm + OFF_K);   // [256][40]
    __half* Vs = (__half*)(csm + OFF_V);   // [256][40]
    __half* Qs = (__half*)(csm + OFF_Q);   // [32][40]  current j-tile
    float*  Sf = (float*)(csm + OFF_S);    // [32][260] f32 logits
    __half* Ph = (__half*)(csm + OFF_S);   // aliased exp tile, stride 520
    const uint32_t ks_b = smaddr(Ks), vs_b = smaddr(Vs);
    const uint32_t qs_b = smaddr(Qs), ph_b = smaddr(Ph);

    const int i = blockIdx.x, h = blockIdx.y;
    const int tid = threadIdx.x;
    const int wid = tid >> 5, lane = tid & 31;
    const int gid = lane >> 2, tig = lane & 3;
    const float scale = 0.17677669529663687f;  // 1/sqrt(32)

    const __half* gk = g_k + ((size_t)i * 256) * CP + h * 32;
    const __half* gv = g_v + ((size_t)i * 256) * CP + h * 32;
    const __half* gq = g_q + ((size_t)i * 256) * CP + h * 32;
    const __half* gg = g_g + ((size_t)i * 256) * CP + h * 32;
    __half*       go = g_o + ((size_t)i * 256) * CP + h * 32;
    const __half* __restrict__ gb = g_b + (size_t)h * NN;

    // stage K, V (once) + Q tile 0
    #pragma unroll
    for (int it = 0; it < 4; ++it) {
        int idx = tid + it * 256;         // 0..1023
        int kk = idx >> 2, u = idx & 3;
        *(uint4*)&Ks[kk * KS_H + u * 8] = *(const uint4*)&gk[(size_t)kk * CP + u * 8];
        *(uint4*)&Vs[kk * KS_H + u * 8] = *(const uint4*)&gv[(size_t)kk * CP + u * 8];
    }
    if (tid < 128) {
        int r = tid >> 2, u = tid & 3;
        *(uint4*)&Qs[r * KS_H + u * 8] = *(const uint4*)&gq[(size_t)r * CP + u * 8];
    }
    __syncthreads();

    // constant B fragment: ones in local col 0 (denominator column)
    const uint32_t bONE = (gid == 0) ? 0x3C003C00u : 0u;

    for (int jt = 0; jt < 8; ++jt) {
        const int j0 = jt * 32;

        // ---- S = Q K^T : warp wid covers keys wid*32..+31, rows 0..31 ----
        {
            float c[2][4][4];
            #pragma unroll
            for (int mf = 0; mf < 2; ++mf)
                #pragma unroll
                for (int nt = 0; nt < 4; ++nt)
                    #pragma unroll
                    for (int q = 0; q < 4; ++q) c[mf][nt][q] = 0.f;

            #pragma unroll
            for (int ks = 0; ks < 2; ++ks) {
                const int k0 = ks * 16;
                uint32_t a[2][4], b[2][4];
                #pragma unroll
                for (int mf = 0; mf < 2; ++mf)
                    ldsm4(a[mf], qs_b +
                        ((mf * 16 + (lane & 15)) * KS_H + k0 + (lane >> 4) * 8) * 2);
                #pragma unroll
                for (int p = 0; p < 2; ++p)
                    ldsm4(b[p], ks_b +
                        ((wid * 32 + p * 16 + (lane & 7) + (lane >> 4) * 8) * KS_H
                         + k0 + ((lane >> 3) & 1) * 8) * 2);
                #pragma unroll
                for (int mf = 0; mf < 2; ++mf)
                    #pragma unroll
                    for (int p = 0; p < 2; ++p)
                        #pragma unroll
                        for (int t = 0; t < 2; ++t)
                            mma16816(c[mf][p * 2 + t], a[mf], b[p][t * 2], b[p][t * 2 + 1]);
            }
            #pragma unroll
            for (int mf = 0; mf < 2; ++mf)
                #pragma unroll
                for (int nt = 0; nt < 4; ++nt) {
                    int r = mf * 16 + gid;
                    int cb = wid * 32 + nt * 8 + tig * 2;
                    *(float2*)&Sf[r * S_S + cb] = make_float2(c[mf][nt][0], c[mf][nt][1]);
                    *(float2*)&Sf[(r + 8) * S_S + cb] = make_float2(c[mf][nt][2], c[mf][nt][3]);
                }
        }
        __syncthreads();

        // ---- softmax exp (streaming, no reductions): warp owns rows wid*4..+3 ----
        #pragma unroll
        for (int rr = 0; rr < 4; ++rr) {
            const int r = wid * 4 + rr;
            const int jg = j0 + r;
            float4 s0 = *(float4*)&Sf[r * S_S + lane * 8];
            float4 s1 = *(float4*)&Sf[r * S_S + lane * 8 + 4];
            uint4 bu = *(const uint4*)&gb[(size_t)jg * 256 + lane * 8];
            float2 bf0 = __half22float2(*(__half2*)&bu.x);
            float2 bf1 = __half22float2(*(__half2*)&bu.y);
            float2 bf2 = __half22float2(*(__half2*)&bu.z);
            float2 bf3 = __half22float2(*(__half2*)&bu.w);
            float e0 = __expf(fmaf(s0.x, scale, bf0.x));
            float e1 = __expf(fmaf(s0.y, scale, bf0.y));
            float e2 = __expf(fmaf(s0.z, scale, bf1.x));
            float e3 = __expf(fmaf(s0.w, scale, bf1.y));
            float e4 = __expf(fmaf(s1.x, scale, bf2.x));
            float e5 = __expf(fmaf(s1.y, scale, bf2.y));
            float e6 = __expf(fmaf(s1.z, scale, bf3.x));
            float e7 = __expf(fmaf(s1.w, scale, bf3.y));
            __half2 hh[4] = {__floats2half2_rn(e0, e1), __floats2half2_rn(e2, e3),
                             __floats2half2_rn(e4, e5), __floats2half2_rn(e6, e7)};
            *(uint4*)&Ph[r * (S_S * 2) + lane * 8] = *(uint4*)hh;
        }
        __syncthreads();

        // ---- pipelined Q stage for next tile (threads 0-127) + PV ----
        if (jt < 7 && tid < 128) {
            int r = tid >> 2, u = tid & 3;
            *(uint4*)&Qs[r * KS_H + u * 8] =
                *(const uint4*)&gq[(size_t)(j0 + 32 + r) * CP + u * 8];
        }

        // ---- O = P V + denominator mma: warp (wm rows, wn cols), K=256 ----
        {
            const int wm = wid & 1, wn = wid >> 1;
            float o[4]  = {0.f, 0.f, 0.f, 0.f};
            float od[4] = {0.f, 0.f, 0.f, 0.f};
            #pragma unroll
            for (int kc = 0; kc < 8; ++kc) {
                const int k0 = kc * 32;
                uint32_t a0[4], a1[4], bv[4];
                ldsm4(a0, ph_b +
                    ((wm * 16 + (lane & 15)) * (S_S * 2) + k0 + (lane >> 4) * 8) * 2);
                ldsm4(a1, ph_b +
                    ((wm * 16 + (lane & 15)) * (S_S * 2) + k0 + 16 + (lane >> 4) * 8) * 2);
                ldsm4t(bv, vs_b + ((k0 + lane) * KS_H + wn * 8) * 2);
                mma16816(o, a0, bv[0], bv[1]);
                mma16816(o, a1, bv[2], bv[3]);
                mma16816(od, a0, bONE, bONE);
                mma16816(od, a1, bONE, bONE);
            }
            // denominator lives in tig==0 lanes (local col 0): broadcast
            float den0 = __shfl_sync(0xffffffffu, od[0], lane & ~3);
            float den1 = __shfl_sync(0xffffffffu, od[2], lane & ~3);
            const int r = wm * 16 + gid;
            const int cc = wn * 8 + tig * 2;
            float i0 = 1.f / den0, i1 = 1.f / den1;
            float2 gf0 = __half22float2(*(const __half2*)&gg[(size_t)(j0 + r) * CP + cc]);
            float2 gf1 = __half22float2(*(const __half2*)&gg[(size_t)(j0 + r + 8) * CP + cc]);
            *(__half2*)&go[(size_t)(j0 + r) * CP + cc] =
                __floats2half2_rn(o[0] * i0 * gf0.x, o[1] * i0 * gf0.y);
            *(__half2*)&go[(size_t)(j0 + r + 8) * CP + cc] =
                __floats2half2_rn(o[2] * i1 * gf1.x, o[3] * i1 * gf1.y);
        }
        __syncthreads();   // protect S/P (next QK writes) + Qs (next QK reads)
    }
}

// ----------------------------------------------------------------- launcher
extern "C" void kernel_launch(void* const* d_in, const int* in_sizes, int n_in,
                              void* d_out, int out_size)
{
    const float* pair  = (const float*)d_in[0];
    const float* gamma = (const float*)d_in[1];
    const float* beta  = (const float*)d_in[2];
    const float* Wq    = (const float*)d_in[3];
    const float* Wk    = (const float*)d_in[4];
    const float* Wv    = (const float*)d_in[5];
    const float* Wb    = (const float*)d_in[6];
    const float* Wg    = (const float*)d_in[7];
    const float* Wout  = (const float*)d_in[8];
    float* out = (float*)d_out;

    cudaFuncSetAttribute(k_proj_mma, cudaFuncAttributeMaxDynamicSharedMemorySize, PJ_SMEM);
    cudaFuncSetAttribute(k_out_mma,  cudaFuncAttributeMaxDynamicSharedMemorySize, PJ_SMEM);
    cudaFuncSetAttribute(k_attn_mma, cudaFuncAttributeMaxDynamicSharedMemorySize, ATTN_SMEM);

    k_wcvt    <<<80, 256>>>(Wq, Wk, Wv, Wg, Wout);
    k_proj_mma<<<NN / 64, 256, PJ_SMEM>>>(pair, gamma, beta, Wb);
    k_attn_mma<<<dim3(N_TOKEN, H), 256, ATTN_SMEM>>>();
    k_out_mma <<<NN / 64, 256, PJ_SMEM>>>(out);
}

// round 17
// speedup vs baseline: 1.2555x; 1.0110x over previous
#include <cuda_runtime.h>
#include <cuda_fp16.h>
#include <math.h>
#include <cstdint>

#define N_TOKEN 256
#define CP 128
#define H 4
#define NN (N_TOKEN * N_TOKEN)

// Scratch (allocation-free: __device__ globals) — activations fp16
__device__ __half g_q [NN * CP];
__device__ __half g_k [NN * CP];
__device__ __half g_v [NN * CP];
__device__ __half g_g [NN * CP];
__device__ __half g_b [H * NN];       // [h][j*256+k] pairwise bias (fp16)
__device__ __half g_o [NN * CP];
__device__ __half g_wh[5 * CP * CP];  // fp16 weights: Wq,Wk,Wv,Wg,Wout

// --------------------------------------------------------------- helpers
__device__ __forceinline__ unsigned smaddr(const void* p) {
    unsigned a;
    asm("{ .reg .u64 t; cvta.to.shared.u64 t, %1; cvt.u32.u64 %0, t; }"
        : "=r"(a) : "l"(p));
    return a;
}
__device__ __forceinline__ void ldsm4(uint32_t r[4], uint32_t a) {
    asm volatile("ldmatrix.sync.aligned.m8n8.x4.shared.b16 {%0,%1,%2,%3}, [%4];"
        : "=r"(r[0]), "=r"(r[1]), "=r"(r[2]), "=r"(r[3]) : "r"(a));
}
__device__ __forceinline__ void ldsm4t(uint32_t r[4], uint32_t a) {
    asm volatile("ldmatrix.sync.aligned.m8n8.x4.trans.shared.b16 {%0,%1,%2,%3}, [%4];"
        : "=r"(r[0]), "=r"(r[1]), "=r"(r[2]), "=r"(r[3]) : "r"(a));
}
__device__ __forceinline__ void mma16816(float c[4], const uint32_t a[4],
                                         uint32_t b0, uint32_t b1) {
    asm volatile(
        "mma.sync.aligned.m16n8k16.row.col.f32.f16.f16.f32 "
        "{%0,%1,%2,%3}, {%4,%5,%6,%7}, {%8,%9}, {%0,%1,%2,%3};"
        : "+f"(c[0]), "+f"(c[1]), "+f"(c[2]), "+f"(c[3])
        : "r"(a[0]), "r"(a[1]), "r"(a[2]), "r"(a[3]), "r"(b0), "r"(b1));
}

// ---------------------------------------------- weight pre-conversion (once)
__global__ void k_wcvt(const float* __restrict__ Wq, const float* __restrict__ Wk,
                       const float* __restrict__ Wv, const float* __restrict__ Wg,
                       const float* __restrict__ Wout)
{
    const float* src[5] = {Wq, Wk, Wv, Wg, Wout};
    int t = blockIdx.x * 256 + threadIdx.x;    // 0..20479
    int m = t >> 12;                           // matrix index
    int e = (t & 4095) * 4;                    // element base
    float4 v = *(const float4*)&src[m][e];
    __half2 hh[2] = {__floats2half2_rn(v.x, v.y), __floats2half2_rn(v.z, v.w)};
    *(uint2*)&g_wh[m * (CP * CP) + e] = *(uint2*)hh;
}

// ------------------- q/k/v/g projection with FUSED LayerNorm + bias (fp16 mma)
#define AS_H 136
#define BS_H 136
#define PJ_SMEM ((64 * AS_H + 128 * BS_H) * 2)

__global__ void __launch_bounds__(256, 3) k_proj_mma(
    const float* __restrict__ pair, const float* __restrict__ gamma,
    const float* __restrict__ beta, const float* __restrict__ Wb)
{
    extern __shared__ __half hsm[];
    __half* As = hsm;                  // [64][136]
    __half* Bs = hsm + 64 * AS_H;      // [128][136] k-major
    const uint32_t as_b = smaddr(As), bs_b = smaddr(Bs);

    const int tid = threadIdx.x;
    const int wid = tid >> 5, lane = tid & 31;
    const int warp_m = wid & 1, warp_n = wid >> 1;
    const int gid = lane >> 2, tig = lane & 3;
    const int m0 = blockIdx.x * 64;

    // ---- fused LN + bias: warp wid handles rows wid*8..+7 ----
    {
        float4 ga = *(const float4*)&gamma[lane * 4];
        float4 be = *(const float4*)&beta[lane * 4];
        #pragma unroll
        for (int rr = 0; rr < 8; ++rr) {
            const int r = wid * 8 + rr;
            const int row = m0 + r;
            float4 x = *(const float4*)&pair[(size_t)row * CP + lane * 4];
            float s = x.x + x.y + x.z + x.w;
            #pragma unroll
            for (int off = 16; off; off >>= 1)
                s += __shfl_xor_sync(0xffffffffu, s, off);
            float mu = s * (1.0f / CP);
            float4 d = make_float4(x.x - mu, x.y - mu, x.z - mu, x.w - mu);
            float sq = d.x * d.x + d.y * d.y + d.z * d.z + d.w * d.w;
            #pragma unroll
            for (int off = 16; off; off >>= 1)
                sq += __shfl_xor_sync(0xffffffffu, sq, off);
            float rstd = rsqrtf(sq * (1.0f / CP) + 1e-5f);
            float pn0 = d.x * rstd * ga.x + be.x;
            float pn1 = d.y * rstd * ga.y + be.y;
            float pn2 = d.z * rstd * ga.z + be.z;
            float pn3 = d.w * rstd * ga.w + be.w;
            __half2 hh[2] = {__floats2half2_rn(pn0, pn1), __floats2half2_rn(pn2, pn3)};
            *(uint2*)&As[r * AS_H + lane * 4] = *(uint2*)hh;

            float pe[4] = {pn0, pn1, pn2, pn3};
            float pb[4] = {0.f, 0.f, 0.f, 0.f};
            #pragma unroll
            for (int e = 0; e < 4; ++e) {
                float4 wb = *(const float4*)&Wb[(lane * 4 + e) * 4];
                pb[0] += pe[e] * wb.x; pb[1] += pe[e] * wb.y;
                pb[2] += pe[e] * wb.z; pb[3] += pe[e] * wb.w;
            }
            #pragma unroll
            for (int h = 0; h < 4; ++h) {
                #pragma unroll
                for (int off = 16; off; off >>= 1)
                    pb[h] += __shfl_xor_sync(0xffffffffu, pb[h], off);
            }
            if (lane < 4) g_b[lane * NN + row] = __float2half_rn(pb[lane]);
        }
    }

    __half* Os[4] = {g_q, g_k, g_v, g_g};

    #pragma unroll
    for (int mat = 0; mat < 4; ++mat) {
        if (mat > 0) __syncthreads();   // Bs reads from previous mat done
        {
            const __half* Wsrc = g_wh + mat * (CP * CP);
            #pragma unroll
            for (int it = 0; it < 8; ++it) {
                int idx = tid + it * 256;        // 0..2047 uint4
                int k = idx >> 4, u = idx & 15;
                *(uint4*)&Bs[k * BS_H + u * 8] = *(const uint4*)&Wsrc[k * CP + u * 8];
            }
        }
        __syncthreads();

        float c[2][4][4];
        #pragma unroll
        for (int mf = 0; mf < 2; ++mf)
            #pragma unroll
            for (int nt = 0; nt < 4; ++nt)
                #pragma unroll
                for (int q = 0; q < 4; ++q) c[mf][nt][q] = 0.f;

        #pragma unroll
        for (int ks = 0; ks < 8; ++ks) {
            const int k0 = ks * 16;
            uint32_t a[2][4], b[2][4];
            #pragma unroll
            for (int mf = 0; mf < 2; ++mf)
                ldsm4(a[mf], as_b +
                    ((warp_m * 32 + mf * 16 + (lane & 15)) * AS_H + k0 + (lane >> 4) * 8) * 2);
            #pragma unroll
            for (int p = 0; p < 2; ++p)
                ldsm4t(b[p], bs_b +
                    ((k0 + (lane & 15)) * BS_H + warp_n * 32 + p * 16 + (lane >> 4) * 8) * 2);
            #pragma unroll
            for (int mf = 0; mf < 2; ++mf)
                #pragma unroll
                for (int p = 0; p < 2; ++p)
                    #pragma unroll
                    for (int t = 0; t < 2; ++t)
                        mma16816(c[mf][p * 2 + t], a[mf], b[p][t * 2], b[p][t * 2 + 1]);
        }

        __half* O = Os[mat];
        #pragma unroll
        for (int mf = 0; mf < 2; ++mf) {
            #pragma unroll
            for (int nt = 0; nt < 4; ++nt) {
                int r  = m0 + warp_m * 32 + mf * 16 + gid;
                int cb = warp_n * 32 + nt * 8 + tig * 2;
                float v0 = c[mf][nt][0], v1 = c[mf][nt][1];
                float v2 = c[mf][nt][2], v3 = c[mf][nt][3];
                if (mat == 3) {
                    v0 = 1.f / (1.f + __expf(-v0));
                    v1 = 1.f / (1.f + __expf(-v1));
                    v2 = 1.f / (1.f + __expf(-v2));
                    v3 = 1.f / (1.f + __expf(-v3));
                }
                *(__half2*)&O[(size_t)r * CP + cb]       = __floats2half2_rn(v0, v1);
                *(__half2*)&O[(size_t)(r + 8) * CP + cb] = __floats2half2_rn(v2, v3);
            }
        }
    }
}

// ----------------------------------------------- output projection (fp16 mma)
__global__ void __launch_bounds__(256, 3) k_out_mma(float* __restrict__ out)
{
    extern __shared__ __half hsm[];
    __half* As = hsm;
    __half* Bs = hsm + 64 * AS_H;
    const uint32_t as_b = smaddr(As), bs_b = smaddr(Bs);

    const int tid = threadIdx.x;
    const int wid = tid >> 5, lane = tid & 31;
    const int warp_m = wid & 1, warp_n = wid >> 1;
    const int gid = lane >> 2, tig = lane & 3;
    const int m0 = blockIdx.x * 64;

    {
        const __half* src = g_o + (size_t)m0 * CP;
        #pragma unroll
        for (int it = 0; it < 4; ++it) {
            int idx = tid + it * 256;
            int r = idx >> 4, u = idx & 15;
            *(uint4*)&As[r * AS_H + u * 8] = *(const uint4*)&src[(size_t)r * CP + u * 8];
        }
    }
    {
        const __half* Wsrc = g_wh + 4 * (CP * CP);
        #pragma unroll
        for (int it = 0; it < 8; ++it) {
            int idx = tid + it * 256;
            int k = idx >> 4, u = idx & 15;
            *(uint4*)&Bs[k * BS_H + u * 8] = *(const uint4*)&Wsrc[k * CP + u * 8];
        }
    }
    __syncthreads();

    float c[2][4][4];
    #pragma unroll
    for (int mf = 0; mf < 2; ++mf)
        #pragma unroll
        for (int nt = 0; nt < 4; ++nt)
            #pragma unroll
            for (int q = 0; q < 4; ++q) c[mf][nt][q] = 0.f;

    #pragma unroll
    for (int ks = 0; ks < 8; ++ks) {
        const int k0 = ks * 16;
        uint32_t a[2][4], b[2][4];
        #pragma unroll
        for (int mf = 0; mf < 2; ++mf)
            ldsm4(a[mf], as_b +
                ((warp_m * 32 + mf * 16 + (lane & 15)) * AS_H + k0 + (lane >> 4) * 8) * 2);
        #pragma unroll
        for (int p = 0; p < 2; ++p)
            ldsm4t(b[p], bs_b +
                ((k0 + (lane & 15)) * BS_H + warp_n * 32 + p * 16 + (lane >> 4) * 8) * 2);
        #pragma unroll
        for (int mf = 0; mf < 2; ++mf)
            #pragma unroll
            for (int p = 0; p < 2; ++p)
                #pragma unroll
                for (int t = 0; t < 2; ++t)
                    mma16816(c[mf][p * 2 + t], a[mf], b[p][t * 2], b[p][t * 2 + 1]);
    }

    #pragma unroll
    for (int mf = 0; mf < 2; ++mf) {
        #pragma unroll
        for (int nt = 0; nt < 4; ++nt) {
            int r  = m0 + warp_m * 32 + mf * 16 + gid;
            int cb = warp_n * 32 + nt * 8 + tig * 2;
            *(float2*)&out[(size_t)r * CP + cb] =
                make_float2(c[mf][nt][0], c[mf][nt][1]);
            *(float2*)&out[(size_t)(r + 8) * CP + cb] =
                make_float2(c[mf][nt][2], c[mf][nt][3]);
        }
    }
}

// ------------------------------------------------ attention (fp16 mma)
// One CTA per (i,h), 8 warps, 8 j-tiles of 32, 3 CTAs/SM.
// exp+bias fused into QK epilogue; denominator via tig-shfl + part table.
// 2 syncs/tile; PV is pure o-mma.
#define KS_H 40          // half stride for K/V/Q rows
#define PS2  264         // half stride for P rows
#define OFF_K 0
#define OFF_V 20480
#define OFF_Q 40960
#define OFF_P 43520
#define OFF_PART 60416
#define ATTN_SMEM 61440

__global__ void __launch_bounds__(256, 3) k_attn_mma()
{
    extern __shared__ char csm[];
    __half* Ks = (__half*)(csm + OFF_K);   // [256][40]
    __half* Vs = (__half*)(csm + OFF_V);   // [256][40]
    __half* Qs = (__half*)(csm + OFF_Q);   // [32][40]  current j-tile
    __half* Ph = (__half*)(csm + OFF_P);   // [32][264] exp tile (half)
    float*  part = (float*)(csm + OFF_PART); // [8][32] per-warp row partials
    const uint32_t ks_b = smaddr(Ks), vs_b = smaddr(Vs);
    const uint32_t qs_b = smaddr(Qs), ph_b = smaddr(Ph);

    const int i = blockIdx.x, h = blockIdx.y;
    const int tid = threadIdx.x;
    const int wid = tid >> 5, lane = tid & 31;
    const int gid = lane >> 2, tig = lane & 3;
    const float scale = 0.17677669529663687f;  // 1/sqrt(32)

    const __half* gk = g_k + ((size_t)i * 256) * CP + h * 32;
    const __half* gv = g_v + ((size_t)i * 256) * CP + h * 32;
    const __half* gq = g_q + ((size_t)i * 256) * CP + h * 32;
    const __half* gg = g_g + ((size_t)i * 256) * CP + h * 32;
    __half*       go = g_o + ((size_t)i * 256) * CP + h * 32;
    const __half* __restrict__ gb = g_b + (size_t)h * NN;

    // stage K, V (once) + Q tile 0
    #pragma unroll
    for (int it = 0; it < 4; ++it) {
        int idx = tid + it * 256;         // 0..1023
        int kk = idx >> 2, u = idx & 3;
        *(uint4*)&Ks[kk * KS_H + u * 8] = *(const uint4*)&gk[(size_t)kk * CP + u * 8];
        *(uint4*)&Vs[kk * KS_H + u * 8] = *(const uint4*)&gv[(size_t)kk * CP + u * 8];
    }
    if (tid < 128) {
        int r = tid >> 2, u = tid & 3;
        *(uint4*)&Qs[r * KS_H + u * 8] = *(const uint4*)&gq[(size_t)r * CP + u * 8];
    }
    __syncthreads();

    for (int jt = 0; jt < 8; ++jt) {
        const int j0 = jt * 32;

        // ---- S = Q K^T, fused exp+bias+partial-denominator ----
        {
            float c[2][4][4];
            #pragma unroll
            for (int mf = 0; mf < 2; ++mf)
                #pragma unroll
                for (int nt = 0; nt < 4; ++nt)
                    #pragma unroll
                    for (int q = 0; q < 4; ++q) c[mf][nt][q] = 0.f;

            #pragma unroll
            for (int ks = 0; ks < 2; ++ks) {
                const int k0 = ks * 16;
                uint32_t a[2][4], b[2][4];
                #pragma unroll
                for (int mf = 0; mf < 2; ++mf)
                    ldsm4(a[mf], qs_b +
                        ((mf * 16 + (lane & 15)) * KS_H + k0 + (lane >> 4) * 8) * 2);
                #pragma unroll
                for (int p = 0; p < 2; ++p)
                    ldsm4(b[p], ks_b +
                        ((wid * 32 + p * 16 + (lane & 7) + (lane >> 4) * 8) * KS_H
                         + k0 + ((lane >> 3) & 1) * 8) * 2);
                #pragma unroll
                for (int mf = 0; mf < 2; ++mf)
                    #pragma unroll
                    for (int p = 0; p < 2; ++p)
                        #pragma unroll
                        for (int t = 0; t < 2; ++t)
                            mma16816(c[mf][p * 2 + t], a[mf], b[p][t * 2], b[p][t * 2 + 1]);
            }

            // epilogue: exp(scale*s + bias) -> Ph (half), row partials -> part
            #pragma unroll
            for (int mf = 0; mf < 2; ++mf) {
                const int r0 = mf * 16 + gid;
                const int jg0 = j0 + r0;
                float ps0 = 0.f, ps1 = 0.f;
                #pragma unroll
                for (int nt = 0; nt < 4; ++nt) {
                    const int cb = wid * 32 + nt * 8 + tig * 2;
                    float2 bf0 = __half22float2(
                        *(const __half2*)&gb[(size_t)jg0 * 256 + cb]);
                    float2 bf1 = __half22float2(
                        *(const __half2*)&gb[(size_t)(jg0 + 8) * 256 + cb]);
                    float e00 = __expf(fmaf(c[mf][nt][0], scale, bf0.x));
                    float e01 = __expf(fmaf(c[mf][nt][1], scale, bf0.y));
                    float e10 = __expf(fmaf(c[mf][nt][2], scale, bf1.x));
                    float e11 = __expf(fmaf(c[mf][nt][3], scale, bf1.y));
                    *(__half2*)&Ph[r0 * PS2 + cb]       = __floats2half2_rn(e00, e01);
                    *(__half2*)&Ph[(r0 + 8) * PS2 + cb] = __floats2half2_rn(e10, e11);
                    ps0 += e00 + e01;
                    ps1 += e10 + e11;
                }
                // reduce across tig group (lanes differing in bits 0-1)
                ps0 += __shfl_xor_sync(0xffffffffu, ps0, 1);
                ps0 += __shfl_xor_sync(0xffffffffu, ps0, 2);
                ps1 += __shfl_xor_sync(0xffffffffu, ps1, 1);
                ps1 += __shfl_xor_sync(0xffffffffu, ps1, 2);
                if (tig == 0) {
                    part[wid * 32 + r0]     = ps0;
                    part[wid * 32 + r0 + 8] = ps1;
                }
            }
        }
        __syncthreads();

        // ---- pipelined Q stage for next tile (threads 0-127) + PV ----
        if (jt < 7 && tid < 128) {
            int r = tid >> 2, u = tid & 3;
            *(uint4*)&Qs[r * KS_H + u * 8] =
                *(const uint4*)&gq[(size_t)(j0 + 32 + r) * CP + u * 8];
        }

        // ---- O = P V (pure): warp (wm rows16, wn cols8), K=256 ----
        {
            const int wm = wid & 1, wn = wid >> 1;
            const int R0 = wm * 16 + gid;
            float den0 = 0.f, den1 = 0.f;
            #pragma unroll
            for (int w = 0; w < 8; ++w) {
                den0 += part[w * 32 + R0];
                den1 += part[w * 32 + R0 + 8];
            }
            float o[4] = {0.f, 0.f, 0.f, 0.f};
            #pragma unroll
            for (int kc = 0; kc < 8; ++kc) {
                const int k0 = kc * 32;
                uint32_t a0[4], a1[4], bv[4];
                ldsm4(a0, ph_b +
                    ((wm * 16 + (lane & 15)) * PS2 + k0 + (lane >> 4) * 8) * 2);
                ldsm4(a1, ph_b +
                    ((wm * 16 + (lane & 15)) * PS2 + k0 + 16 + (lane >> 4) * 8) * 2);
                ldsm4t(bv, vs_b + ((k0 + lane) * KS_H + wn * 8) * 2);
                mma16816(o, a0, bv[0], bv[1]);
                mma16816(o, a1, bv[2], bv[3]);
            }
            const int cc = wn * 8 + tig * 2;
            float i0 = 1.f / den0, i1 = 1.f / den1;
            float2 gf0 = __half22float2(*(const __half2*)&gg[(size_t)(j0 + R0) * CP + cc]);
            float2 gf1 = __half22float2(*(const __half2*)&gg[(size_t)(j0 + R0 + 8) * CP + cc]);
            *(__half2*)&go[(size_t)(j0 + R0) * CP + cc] =
                __floats2half2_rn(o[0] * i0 * gf0.x, o[1] * i0 * gf0.y);
            *(__half2*)&go[(size_t)(j0 + R0 + 8) * CP + cc] =
                __floats2half2_rn(o[2] * i1 * gf1.x, o[3] * i1 * gf1.y);
        }
        __syncthreads();   // protect Ph/part (next QK writes) + Qs (next QK reads)
    }
}

// ----------------------------------------------------------------- launcher
extern "C" void kernel_launch(void* const* d_in, const int* in_sizes, int n_in,
                              void* d_out, int out_size)
{
    const float* pair  = (const float*)d_in[0];
    const float* gamma = (const float*)d_in[1];
    const float* beta  = (const float*)d_in[2];
    const float* Wq    = (const float*)d_in[3];
    const float* Wk    = (const float*)d_in[4];
    const float* Wv    = (const float*)d_in[5];
    const float* Wb    = (const float*)d_in[6];
    const float* Wg    = (const float*)d_in[7];
    const float* Wout  = (const float*)d_in[8];
    float* out = (float*)d_out;

    cudaFuncSetAttribute(k_proj_mma, cudaFuncAttributeMaxDynamicSharedMemorySize, PJ_SMEM);
    cudaFuncSetAttribute(k_out_mma,  cudaFuncAttributeMaxDynamicSharedMemorySize, PJ_SMEM);
    cudaFuncSetAttribute(k_attn_mma, cudaFuncAttributeMaxDynamicSharedMemorySize, ATTN_SMEM);

    k_wcvt    <<<80, 256>>>(Wq, Wk, Wv, Wg, Wout);
    k_proj_mma<<<NN / 64, 256, PJ_SMEM>>>(pair, gamma, beta, Wb);
    k_attn_mma<<<dim3(N_TOKEN, H), 256, ATTN_SMEM>>>();
    k_out_mma <<<NN / 64, 256, PJ_SMEM>>>(out);
}